// round 2
// baseline (speedup 1.0000x reference)
#include <cuda_runtime.h>
#include <math.h>

#define Nn 100000
#define Ee 1600000
#define Dd 32
#define Kk 1024
#define HALF_E (Ee/2)
#define HALF_N (Nn/2)

// JAX threefry mode: 1 = partitionable (modern default), 0 = legacy split-iota
#define PARTITIONABLE 1

// ---------------- scratch (device globals; no allocation allowed) ----------------
__device__ int      g_counts[Nn];
__device__ int      g_rowptr[Nn + 1];
__device__ int      g_cursor[Nn];
__device__ int      g_eid[Ee];
__device__ int      g_col[Ee];
__device__ float    g_v0[Ee], g_v1[Ee], g_v2[Ee], g_v3[Ee];   // CSR order, per dropout depth
__device__ float    g_order0[Nn], g_order1[Nn], g_order2[Nn];
__device__ float    g_embA[Nn * Dd], g_embB[Nn * Dd], g_embS[Nn * Dd];
__device__ float    g_numA[Nn], g_numB[Nn], g_numS[Nn];
__device__ unsigned g_keys[Nn];
__device__ unsigned g_kth;
__device__ int      g_mEq;
__device__ int      g_cntG, g_cntE;
__device__ unsigned long long g_candG[2048];
__device__ int      g_candE[2048];

// ---------------- threefry-2x32 (JAX schedule) ----------------
__host__ __device__ __forceinline__ void tf2x32(unsigned k0, unsigned k1,
                                                unsigned x0, unsigned x1,
                                                unsigned& o0, unsigned& o1) {
    unsigned k2 = k0 ^ k1 ^ 0x1BD11BDAu;
    x0 += k0; x1 += k1;
#define TFR(r) { x0 += x1; x1 = (x1 << r) | (x1 >> (32 - r)); x1 ^= x0; }
    TFR(13) TFR(15) TFR(26) TFR(6)   x0 += k1; x1 += k2 + 1u;
    TFR(17) TFR(29) TFR(16) TFR(24)  x0 += k2; x1 += k0 + 2u;
    TFR(13) TFR(15) TFR(26) TFR(6)   x0 += k0; x1 += k1 + 3u;
    TFR(17) TFR(29) TFR(16) TFR(24)  x0 += k1; x1 += k2 + 4u;
    TFR(13) TFR(15) TFR(26) TFR(6)   x0 += k2; x1 += k0 + 5u;
#undef TFR
    o0 = x0; o1 = x1;
}

__device__ __forceinline__ float bits_to_uniform(unsigned bits) {
    return __fsub_rn(__uint_as_float((bits >> 9) | 0x3f800000u), 1.0f);
}

// per-edge 32-bit draw under a folded key
__device__ __forceinline__ unsigned edge_bits(unsigned k0, unsigned k1, int e) {
#if PARTITIONABLE
    unsigned o0, o1;
    tf2x32(k0, k1, 0u, (unsigned)e, o0, o1);
    return o0 ^ o1;
#else
    unsigned o0, o1;
    if (e < HALF_E) { tf2x32(k0, k1, (unsigned)e, (unsigned)(e + HALF_E), o0, o1); return o0; }
    else            { tf2x32(k0, k1, (unsigned)(e - HALF_E), (unsigned)e, o0, o1); return o1; }
#endif
}

// ---------------- CSR build ----------------
__global__ void init_kernel() {
    int i = blockIdx.x * blockDim.x + threadIdx.x;
    if (i < Nn) g_counts[i] = 0;
}

__global__ void count_kernel(const int* __restrict__ rows) {
    int e = blockIdx.x * blockDim.x + threadIdx.x;
    if (e < Ee) atomicAdd(&g_counts[rows[e]], 1);
}

__global__ void scan_kernel() {
    __shared__ int sh[1024];
    __shared__ int carry;
    int tid = threadIdx.x;
    if (tid == 0) carry = 0;
    __syncthreads();
    for (int base = 0; base < Nn; base += 1024) {
        int idx = base + tid;
        int v = (idx < Nn) ? g_counts[idx] : 0;
        sh[tid] = v;
        __syncthreads();
        for (int off = 1; off < 1024; off <<= 1) {
            int t = (tid >= off) ? sh[tid - off] : 0;
            __syncthreads();
            sh[tid] += t;
            __syncthreads();
        }
        int incl = sh[tid];
        int excl = carry + incl - v;
        if (idx < Nn) { g_rowptr[idx] = excl; g_cursor[idx] = excl; }
        __syncthreads();
        if (tid == 1023) carry += sh[1023];
        __syncthreads();
    }
    if (tid == 0) g_rowptr[Nn] = carry;
}

__global__ void scatter_kernel(const int* __restrict__ rows) {
    int e = blockIdx.x * blockDim.x + threadIdx.x;
    if (e >= Ee) return;
    int pos = atomicAdd(&g_cursor[rows[e]], 1);
    g_eid[pos] = e;
}

// Stable in-row sort by edge id; compute dropout value chain per edge via threefry;
// fill CSR cols + SoA vals; compute orders O0..O2 sequentially in edge order.
__global__ void sortfill_kernel(const int* __restrict__ cols,
                                const float* __restrict__ adj,
                                unsigned a0, unsigned a1, unsigned b0, unsigned b1,
                                unsigned c0, unsigned c1) {
    int r = blockIdx.x * blockDim.x + threadIdx.x;
    if (r >= Nn) return;
    int s = g_rowptr[r], t = g_rowptr[r + 1];
    int deg = t - s;
    if (deg <= 128) {
        int le[128];
        for (int q = 0; q < deg; q++) le[q] = g_eid[s + q];
        for (int a = 1; a < deg; a++) {
            int x = le[a]; int b = a - 1;
            while (b >= 0 && le[b] > x) { le[b + 1] = le[b]; b--; }
            le[b + 1] = x;
        }
        for (int q = 0; q < deg; q++) g_eid[s + q] = le[q];
    } else {
        for (int a = s + 1; a < t; a++) {
            int x = g_eid[a]; int b = a - 1;
            while (b >= s && g_eid[b] > x) { g_eid[b + 1] = g_eid[b]; b--; }
            g_eid[b + 1] = x;
        }
    }
    float o0a = 0.f, o1a = 0.f, o2a = 0.f;
    for (int q = s; q < t; q++) {
        int eid = g_eid[q];
        g_col[q] = cols[eid];
        float v0 = adj[eid];
        float k0f = floorf(__fadd_rn(bits_to_uniform(edge_bits(a0, a1, eid)), 0.5f));
        float v1 = __fmul_rn(v0, k0f);
        float k1f = floorf(__fadd_rn(bits_to_uniform(edge_bits(b0, b1, eid)), 0.25f));
        float v2 = __fmul_rn(v1, k1f);
        float k2f = floorf(__fadd_rn(bits_to_uniform(edge_bits(c0, c1, eid)), 0.125f));
        float v3 = __fmul_rn(v2, k2f);
        g_v0[q] = v0; g_v1[q] = v1; g_v2[q] = v2; g_v3[q] = v3;
        o0a = __fadd_rn(o0a, v0);
        o1a = __fadd_rn(o1a, v1);
        o2a = __fadd_rn(o2a, v2);
    }
    g_order0[r] = o0a; g_order1[r] = o1a; g_order2[r] = o2a;
}

// ---------------- propagation ----------------
// e0 = spmm(v0, X) - X ; n0 = O0. One warp per node, lane = dim.
__global__ void emb0_kernel(const float* __restrict__ X) {
    int w = (blockIdx.x * blockDim.x + threadIdx.x) >> 5;
    int lane = threadIdx.x & 31;
    if (w >= Nn) return;
    int s = g_rowptr[w], t = g_rowptr[w + 1];
    float acc = 0.f;
    for (int p = s; p < t; p++) {
        int c = g_col[p];
        float v = g_v0[p];
        acc = __fadd_rn(acc, __fmul_rn(v, X[c * Dd + lane]));
    }
    float e0 = __fsub_rn(acc, X[w * Dd + lane]);
    g_embA[w * Dd + lane] = e0;
    g_embS[w * Dd + lane] = e0;
    if (lane == 0) {
        float o = g_order0[w];
        g_numA[w] = o;
        g_numS[w] = o;
    }
}

// e_i = spmm(v_i, e) - e - O*e ;  n_i = spmm(v_i, n) - n - O
__global__ void iter_kernel(int sel, int comp) {
    const float* vals = (comp == 1) ? g_v1 : ((comp == 2) ? g_v2 : g_v3);
    const float* ord  = (comp == 1) ? g_order0 : ((comp == 2) ? g_order1 : g_order2);
    const float* cur  = sel ? g_embB : g_embA;
    float*       nxt  = sel ? g_embA : g_embB;
    const float* curn = sel ? g_numB : g_numA;
    float*       nxtn = sel ? g_numA : g_numB;
    int w = (blockIdx.x * blockDim.x + threadIdx.x) >> 5;
    int lane = threadIdx.x & 31;
    if (w >= Nn) return;
    int s = g_rowptr[w], t = g_rowptr[w + 1];
    float accE = 0.f, accN = 0.f;
    for (int p = s; p < t; p++) {
        int c = g_col[p];
        float v = vals[p];
        accE = __fadd_rn(accE, __fmul_rn(v, cur[c * Dd + lane]));
        accN = __fadd_rn(accN, __fmul_rn(v, curn[c]));
    }
    float o = ord[w];
    float ce = cur[w * Dd + lane];
    float outE = __fsub_rn(__fsub_rn(accE, ce), __fmul_rn(o, ce));
    nxt[w * Dd + lane] = outE;
    g_embS[w * Dd + lane] = __fadd_rn(g_embS[w * Dd + lane], outE);
    if (lane == 0) {
        float cn = curn[w];
        float outN = __fsub_rn(__fsub_rn(accN, cn), o);
        nxtn[w] = outN;
        g_numS[w] = __fadd_rn(g_numS[w], outN);
    }
}

// ---------------- scores (strict in-order D reductions) ----------------
__global__ void score_kernel(const float* __restrict__ X, float* score_out) {
    int w = (blockIdx.x * blockDim.x + threadIdx.x) >> 5;
    int lane = threadIdx.x & 31;
    if (w >= Nn) return;
    float den = __fadd_rn(g_numS[w], 1e-8f);
    float sv = __fdiv_rn(g_embS[w * Dd + lane], den);
    float ev = X[w * Dd + lane];

    float p1 = __fmul_rn(sv, sv);
    float sq = 0.f;
#pragma unroll
    for (int d = 0; d < 32; d++) sq = __fadd_rn(sq, __shfl_sync(0xffffffffu, p1, d));
    float nr = fmaxf(__fsqrt_rn(sq), 1e-12f);

    float p2 = __fmul_rn(ev, ev);
    float sq2 = 0.f;
#pragma unroll
    for (int d = 0; d < 32; d++) sq2 = __fadd_rn(sq2, __shfl_sync(0xffffffffu, p2, d));
    float nr2 = fmaxf(__fsqrt_rn(sq2), 1e-12f);

    float prod = __fmul_rn(__fdiv_rn(sv, nr), __fdiv_rn(ev, nr2));
    float dot = 0.f;
#pragma unroll
    for (int d = 0; d < 32; d++) dot = __fadd_rn(dot, __shfl_sync(0xffffffffu, prod, d));

    if (lane == 0) {
        unsigned bits;
#if PARTITIONABLE
        unsigned o0, o1;
        tf2x32(0u, 7u, 0u, (unsigned)w, o0, o1);
        bits = o0 ^ o1;
#else
        unsigned o0, o1;
        if (w < HALF_N) { tf2x32(0u, 7u, (unsigned)w, (unsigned)(w + HALF_N), o0, o1); bits = o0; }
        else            { tf2x32(0u, 7u, (unsigned)(w - HALF_N), (unsigned)w, o0, o1); bits = o1; }
#endif
        float u = bits_to_uniform(bits);
        float lu = (float)log((double)u);
        float g  = -(float)log((double)(-lu));
        float score = __fadd_rn(dot, g);
        if (score_out) score_out[w] = score;
        unsigned ub = __float_as_uint(score);
        g_keys[w] = (ub & 0x80000000u) ? ~ub : (ub | 0x80000000u);
    }
}

// ---------------- top-k: radix select -> compact -> bitonic ----------------
__global__ void select_kernel() {
    __shared__ int hist[256];
    __shared__ unsigned s_prefix, s_mask;
    __shared__ int s_k;
    int tid = threadIdx.x;
    if (tid == 0) { s_prefix = 0u; s_mask = 0u; s_k = Kk; }
    __syncthreads();
    for (int shift = 24; shift >= 0; shift -= 8) {
        hist[tid] = 0;
        __syncthreads();
        unsigned mask = s_mask, pref = s_prefix;
        for (int i = tid; i < Nn; i += 256) {
            unsigned key = g_keys[i];
            if ((key & mask) == pref) atomicAdd(&hist[(key >> shift) & 255u], 1);
        }
        __syncthreads();
        if (tid == 0) {
            int k = s_k;
            int v = 255;
            for (; v > 0; v--) { int c = hist[v]; if (k <= c) break; k -= c; }
            s_prefix = pref | ((unsigned)v << shift);
            s_mask = mask | (0xFFu << shift);
            s_k = k;
        }
        __syncthreads();
    }
    if (tid == 0) {
        g_kth = s_prefix;      // threshold key (K-th largest)
        g_mEq = s_k;           // how many threshold-equal elements to keep
        g_cntG = 0; g_cntE = 0;
    }
}

__global__ void compact_kernel() {
    int i = blockIdx.x * blockDim.x + threadIdx.x;
    if (i >= Nn) return;
    unsigned key = g_keys[i];
    unsigned T = g_kth;
    if (key > T) {
        int p = atomicAdd(&g_cntG, 1);
        if (p < 2048) g_candG[p] = (((unsigned long long)(~key)) << 32) | (unsigned)i;
    } else if (key == T) {
        int p = atomicAdd(&g_cntE, 1);
        if (p < 2048) g_candE[p] = i;
    }
}

__global__ void finalsort_kernel(float* cand_out) {
    __shared__ unsigned long long sg[1024];
    __shared__ int se[2048];
    int tid = threadIdx.x;
    int cntG = g_cntG; if (cntG > 1024) cntG = 1024;
    int cntE = g_cntE; if (cntE > 2048) cntE = 2048;
    sg[tid] = (tid < cntG) ? g_candG[tid] : 0xFFFFFFFFFFFFFFFFull;
    se[tid]        = (tid < cntE)        ? g_candE[tid]        : 0x7FFFFFFF;
    se[tid + 1024] = (tid + 1024 < cntE) ? g_candE[tid + 1024] : 0x7FFFFFFF;
    __syncthreads();
    // bitonic ascending sort of sg (composite: ~key desc-key, asc idx)
    for (int k = 2; k <= 1024; k <<= 1)
        for (int j = k >> 1; j > 0; j >>= 1) {
            int ixj = tid ^ j;
            if (ixj > tid) {
                bool up = ((tid & k) == 0);
                unsigned long long a = sg[tid], b = sg[ixj];
                if ((a > b) == up) { sg[tid] = b; sg[ixj] = a; }
            }
            __syncthreads();
        }
    // bitonic ascending sort of se (2048 elems, 1024 threads)
    for (int k = 2; k <= 2048; k <<= 1)
        for (int j = k >> 1; j > 0; j >>= 1) {
            for (int t = tid; t < 2048; t += 1024) {
                int ixj = t ^ j;
                if (ixj > t) {
                    bool up = ((t & k) == 0);
                    int a = se[t], b = se[ixj];
                    if ((a > b) == up) { se[t] = b; se[ixj] = a; }
                }
            }
            __syncthreads();
        }
    if (tid < Kk && cand_out) {
        int idx = (tid < cntG) ? (int)(sg[tid] & 0xFFFFFFFFull) : se[tid - cntG];
        cand_out[tid] = (float)idx;
    }
}

// ---------------- launch ----------------
extern "C" void kernel_launch(void* const* d_in, const int* in_sizes, int n_in,
                              void* d_out, int out_size) {
    const int*   edge_index = (const int*)d_in[0];   // [2, E]
    const float* adj_values = (const float*)d_in[1]; // [E]
    const float* embeds     = (const float*)d_in[2]; // [N, D]
    const int* rows = edge_index;
    const int* cols = edge_index + Ee;
    float* out = (float*)d_out;

    float* score_out = nullptr;
    float* cand_out  = nullptr;
    if (out_size >= Nn + Kk)      { score_out = out; cand_out = out + Nn; }
    else if (out_size == Nn)      { score_out = out; }
    else if (out_size == Kk)      { cand_out = out; }
    else                          { score_out = out; }

    // folded dropout keys on host: fold_in(key(42), i) = threefry((0,42),(0,i))
    unsigned fk[3][2];
    for (int i = 0; i < 3; i++) tf2x32(0u, 42u, 0u, (unsigned)i, fk[i][0], fk[i][1]);

    const int TB = 256;
    init_kernel<<<(Nn + TB - 1) / TB, TB>>>();
    count_kernel<<<(Ee + TB - 1) / TB, TB>>>(rows);
    scan_kernel<<<1, 1024>>>();
    scatter_kernel<<<(Ee + TB - 1) / TB, TB>>>(rows);
    sortfill_kernel<<<(Nn + TB - 1) / TB, TB>>>(cols, adj_values,
                                                fk[0][0], fk[0][1],
                                                fk[1][0], fk[1][1],
                                                fk[2][0], fk[2][1]);
    int warpBlocks = (Nn * 32 + TB - 1) / TB;
    emb0_kernel<<<warpBlocks, TB>>>(embeds);
    iter_kernel<<<warpBlocks, TB>>>(0, 1);
    iter_kernel<<<warpBlocks, TB>>>(1, 2);
    iter_kernel<<<warpBlocks, TB>>>(0, 3);
    score_kernel<<<warpBlocks, TB>>>(embeds, score_out);
    select_kernel<<<1, 256>>>();
    compact_kernel<<<(Nn + TB - 1) / TB, TB>>>();
    finalsort_kernel<<<1, 1024>>>(cand_out);
}

// round 3
// speedup vs baseline: 1.2206x; 1.2206x over previous
#include <cuda_runtime.h>
#include <math.h>

#define Nn 100000
#define Ee 1600000
#define Dd 32
#define Kk 1024
#define HALF_E (Ee/2)
#define HALF_N (Nn/2)

// JAX threefry mode: 1 = partitionable (modern default), 0 = legacy split-iota
#define PARTITIONABLE 1

#define SCAN_B 1024
#define NBLK ((Nn + SCAN_B - 1) / SCAN_B)   // 98

// ---------------- scratch (device globals; no allocation allowed) ----------------
__device__ int      g_counts[Nn];
__device__ int      g_rowptr[Nn + 1];
__device__ int      g_cursor[Nn];
__device__ int      g_eid[Ee];
__device__ float2   g_cv0[Ee], g_cv1[Ee], g_cv2[Ee], g_cv3[Ee]; // (col, val) CSR order
__device__ float    g_order0[Nn], g_order1[Nn], g_order2[Nn];
__device__ float    g_embA[Nn * Dd], g_embB[Nn * Dd], g_embS[Nn * Dd];
__device__ float    g_numA[Nn], g_numB[Nn], g_numS[Nn];
__device__ unsigned g_keys[Nn];
__device__ unsigned g_kth;
__device__ int      g_cntG, g_cntE;
__device__ unsigned long long g_candG[2048];
__device__ int      g_candE[2048];
__device__ int      g_bsum[NBLK];
__device__ int      g_boff[NBLK + 1];

// ---------------- threefry-2x32 (JAX schedule) ----------------
__host__ __device__ __forceinline__ void tf2x32(unsigned k0, unsigned k1,
                                                unsigned x0, unsigned x1,
                                                unsigned& o0, unsigned& o1) {
    unsigned k2 = k0 ^ k1 ^ 0x1BD11BDAu;
    x0 += k0; x1 += k1;
#define TFR(r) { x0 += x1; x1 = (x1 << r) | (x1 >> (32 - r)); x1 ^= x0; }
    TFR(13) TFR(15) TFR(26) TFR(6)   x0 += k1; x1 += k2 + 1u;
    TFR(17) TFR(29) TFR(16) TFR(24)  x0 += k2; x1 += k0 + 2u;
    TFR(13) TFR(15) TFR(26) TFR(6)   x0 += k0; x1 += k1 + 3u;
    TFR(17) TFR(29) TFR(16) TFR(24)  x0 += k1; x1 += k2 + 4u;
    TFR(13) TFR(15) TFR(26) TFR(6)   x0 += k2; x1 += k0 + 5u;
#undef TFR
    o0 = x0; o1 = x1;
}

__device__ __forceinline__ float bits_to_uniform(unsigned bits) {
    return __fsub_rn(__uint_as_float((bits >> 9) | 0x3f800000u), 1.0f);
}

__device__ __forceinline__ unsigned edge_bits(unsigned k0, unsigned k1, int e) {
#if PARTITIONABLE
    unsigned o0, o1;
    tf2x32(k0, k1, 0u, (unsigned)e, o0, o1);
    return o0 ^ o1;
#else
    unsigned o0, o1;
    if (e < HALF_E) { tf2x32(k0, k1, (unsigned)e, (unsigned)(e + HALF_E), o0, o1); return o0; }
    else            { tf2x32(k0, k1, (unsigned)(e - HALF_E), (unsigned)e, o0, o1); return o1; }
#endif
}

__device__ __forceinline__ float2 packcv(int c, float v) {
    float2 r; r.x = __int_as_float(c); r.y = v; return r;
}

// ---------------- CSR build ----------------
__global__ void init_kernel() {
    int i = blockIdx.x * blockDim.x + threadIdx.x;
    if (i < Nn) g_counts[i] = 0;
}

__global__ void count_kernel(const int* __restrict__ rows) {
    int e = blockIdx.x * blockDim.x + threadIdx.x;
    if (e < Ee) atomicAdd(&g_counts[rows[e]], 1);
}

// per-block exclusive scan -> rowptr (local), block total -> g_bsum
__global__ void scanA_kernel() {
    __shared__ int sh[SCAN_B];
    int tid = threadIdx.x;
    int idx = blockIdx.x * SCAN_B + tid;
    int v = (idx < Nn) ? g_counts[idx] : 0;
    sh[tid] = v;
    __syncthreads();
#pragma unroll
    for (int off = 1; off < SCAN_B; off <<= 1) {
        int t = (tid >= off) ? sh[tid - off] : 0;
        __syncthreads();
        sh[tid] += t;
        __syncthreads();
    }
    if (idx < Nn) g_rowptr[idx] = sh[tid] - v;   // block-local exclusive
    if (tid == SCAN_B - 1) g_bsum[blockIdx.x] = sh[tid];
}

__global__ void scanB_kernel() {
    __shared__ int sh[NBLK];
    int tid = threadIdx.x;
    if (tid < NBLK) sh[tid] = g_bsum[tid];
    __syncthreads();
    if (tid == 0) {
        int acc = 0;
        for (int b = 0; b < NBLK; b++) { int t = sh[b]; g_boff[b] = acc; acc += t; }
        g_boff[NBLK] = acc;
        g_rowptr[Nn] = acc;
    }
}

__global__ void scanC_kernel() {
    int idx = blockIdx.x * SCAN_B + threadIdx.x;
    if (idx < Nn) {
        int v = g_rowptr[idx] + g_boff[blockIdx.x];
        g_rowptr[idx] = v;
        g_cursor[idx] = v;
    }
}

__global__ void scatter_kernel(const int* __restrict__ rows) {
    int e = blockIdx.x * blockDim.x + threadIdx.x;
    if (e >= Ee) return;
    int pos = atomicAdd(&g_cursor[rows[e]], 1);
    g_eid[pos] = e;
}

// Stable in-row sort by edge id; dropout value chain via threefry; fill packed CSR;
// compute orders O0..O2 sequentially in edge order.
__global__ void sortfill_kernel(const int* __restrict__ cols,
                                const float* __restrict__ adj,
                                unsigned a0, unsigned a1, unsigned b0, unsigned b1,
                                unsigned c0, unsigned c1) {
    int r = blockIdx.x * blockDim.x + threadIdx.x;
    if (r >= Nn) return;
    int s = g_rowptr[r], t = g_rowptr[r + 1];
    int deg = t - s;
    if (deg <= 128) {
        int le[128];
        for (int q = 0; q < deg; q++) le[q] = g_eid[s + q];
        for (int a = 1; a < deg; a++) {
            int x = le[a]; int b = a - 1;
            while (b >= 0 && le[b] > x) { le[b + 1] = le[b]; b--; }
            le[b + 1] = x;
        }
        for (int q = 0; q < deg; q++) g_eid[s + q] = le[q];
    } else {
        for (int a = s + 1; a < t; a++) {
            int x = g_eid[a]; int b = a - 1;
            while (b >= s && g_eid[b] > x) { g_eid[b + 1] = g_eid[b]; b--; }
            g_eid[b + 1] = x;
        }
    }
    float o0a = 0.f, o1a = 0.f, o2a = 0.f;
    for (int q = s; q < t; q++) {
        int eid = g_eid[q];
        int c = cols[eid];
        float v0 = adj[eid];
        float k0f = floorf(__fadd_rn(bits_to_uniform(edge_bits(a0, a1, eid)), 0.5f));
        float v1 = __fmul_rn(v0, k0f);
        float k1f = floorf(__fadd_rn(bits_to_uniform(edge_bits(b0, b1, eid)), 0.25f));
        float v2 = __fmul_rn(v1, k1f);
        float k2f = floorf(__fadd_rn(bits_to_uniform(edge_bits(c0, c1, eid)), 0.125f));
        float v3 = __fmul_rn(v2, k2f);
        g_cv0[q] = packcv(c, v0);
        g_cv1[q] = packcv(c, v1);
        g_cv2[q] = packcv(c, v2);
        g_cv3[q] = packcv(c, v3);
        o0a = __fadd_rn(o0a, v0);
        o1a = __fadd_rn(o1a, v1);
        o2a = __fadd_rn(o2a, v2);
    }
    g_order0[r] = o0a; g_order1[r] = o1a; g_order2[r] = o2a;
}

// ---------------- propagation ----------------
// e0 = spmm(v0, X) - X ; n0 = O0. One warp per node, lane = dim.
// Unroll-by-4: loads batched for MLP; ADD ORDER STRICTLY SEQUENTIAL in p.
__global__ void emb0_kernel(const float* __restrict__ X) {
    int w = (blockIdx.x * blockDim.x + threadIdx.x) >> 5;
    int lane = threadIdx.x & 31;
    if (w >= Nn) return;
    int s = g_rowptr[w], t = g_rowptr[w + 1];
    float acc = 0.f;
    int p = s;
    for (; p + 4 <= t; p += 4) {
        float2 a0 = g_cv0[p], a1 = g_cv0[p + 1], a2 = g_cv0[p + 2], a3 = g_cv0[p + 3];
        int c0 = __float_as_int(a0.x), c1 = __float_as_int(a1.x);
        int c2 = __float_as_int(a2.x), c3 = __float_as_int(a3.x);
        float x0 = X[c0 * Dd + lane], x1 = X[c1 * Dd + lane];
        float x2 = X[c2 * Dd + lane], x3 = X[c3 * Dd + lane];
        acc = __fadd_rn(acc, __fmul_rn(a0.y, x0));
        acc = __fadd_rn(acc, __fmul_rn(a1.y, x1));
        acc = __fadd_rn(acc, __fmul_rn(a2.y, x2));
        acc = __fadd_rn(acc, __fmul_rn(a3.y, x3));
    }
    for (; p < t; p++) {
        float2 a = g_cv0[p];
        acc = __fadd_rn(acc, __fmul_rn(a.y, X[__float_as_int(a.x) * Dd + lane]));
    }
    float e0 = __fsub_rn(acc, X[w * Dd + lane]);
    g_embA[w * Dd + lane] = e0;
    g_embS[w * Dd + lane] = e0;
    if (lane == 0) {
        float o = g_order0[w];
        g_numA[w] = o;
        g_numS[w] = o;
    }
}

// e_i = spmm(v_i, e) - e - O*e ;  n_i = spmm(v_i, n) - n - O
template <int SEL, int COMP>
__global__ void iter_kernel() {
    const float2* __restrict__ cv = (COMP == 1) ? g_cv1 : ((COMP == 2) ? g_cv2 : g_cv3);
    const float* __restrict__ ord = (COMP == 1) ? g_order0 : ((COMP == 2) ? g_order1 : g_order2);
    const float* __restrict__ cur  = SEL ? g_embB : g_embA;
    float*       __restrict__ nxt  = SEL ? g_embA : g_embB;
    const float* __restrict__ curn = SEL ? g_numB : g_numA;
    float*       __restrict__ nxtn = SEL ? g_numA : g_numB;
    int w = (blockIdx.x * blockDim.x + threadIdx.x) >> 5;
    int lane = threadIdx.x & 31;
    if (w >= Nn) return;
    int s = g_rowptr[w], t = g_rowptr[w + 1];
    float accE = 0.f, accN = 0.f;
    int p = s;
    for (; p + 4 <= t; p += 4) {
        float2 a0 = cv[p], a1 = cv[p + 1], a2 = cv[p + 2], a3 = cv[p + 3];
        int c0 = __float_as_int(a0.x), c1 = __float_as_int(a1.x);
        int c2 = __float_as_int(a2.x), c3 = __float_as_int(a3.x);
        float x0 = cur[c0 * Dd + lane], x1 = cur[c1 * Dd + lane];
        float x2 = cur[c2 * Dd + lane], x3 = cur[c3 * Dd + lane];
        float n0 = curn[c0], n1 = curn[c1], n2 = curn[c2], n3 = curn[c3];
        accE = __fadd_rn(accE, __fmul_rn(a0.y, x0));
        accN = __fadd_rn(accN, __fmul_rn(a0.y, n0));
        accE = __fadd_rn(accE, __fmul_rn(a1.y, x1));
        accN = __fadd_rn(accN, __fmul_rn(a1.y, n1));
        accE = __fadd_rn(accE, __fmul_rn(a2.y, x2));
        accN = __fadd_rn(accN, __fmul_rn(a2.y, n2));
        accE = __fadd_rn(accE, __fmul_rn(a3.y, x3));
        accN = __fadd_rn(accN, __fmul_rn(a3.y, n3));
    }
    for (; p < t; p++) {
        float2 a = cv[p];
        int c = __float_as_int(a.x);
        accE = __fadd_rn(accE, __fmul_rn(a.y, cur[c * Dd + lane]));
        accN = __fadd_rn(accN, __fmul_rn(a.y, curn[c]));
    }
    float o = ord[w];
    float ce = cur[w * Dd + lane];
    float outE = __fsub_rn(__fsub_rn(accE, ce), __fmul_rn(o, ce));
    nxt[w * Dd + lane] = outE;
    g_embS[w * Dd + lane] = __fadd_rn(g_embS[w * Dd + lane], outE);
    if (lane == 0) {
        float cn = curn[w];
        float outN = __fsub_rn(__fsub_rn(accN, cn), o);
        nxtn[w] = outN;
        g_numS[w] = __fadd_rn(g_numS[w], outN);
    }
}

// ---------------- scores (strict in-order D reductions) ----------------
__global__ void score_kernel(const float* __restrict__ X, float* score_out) {
    int w = (blockIdx.x * blockDim.x + threadIdx.x) >> 5;
    int lane = threadIdx.x & 31;
    if (w >= Nn) return;
    float den = __fadd_rn(g_numS[w], 1e-8f);
    float sv = __fdiv_rn(g_embS[w * Dd + lane], den);
    float ev = X[w * Dd + lane];

    float p1 = __fmul_rn(sv, sv);
    float sq = 0.f;
#pragma unroll
    for (int d = 0; d < 32; d++) sq = __fadd_rn(sq, __shfl_sync(0xffffffffu, p1, d));
    float nr = fmaxf(__fsqrt_rn(sq), 1e-12f);

    float p2 = __fmul_rn(ev, ev);
    float sq2 = 0.f;
#pragma unroll
    for (int d = 0; d < 32; d++) sq2 = __fadd_rn(sq2, __shfl_sync(0xffffffffu, p2, d));
    float nr2 = fmaxf(__fsqrt_rn(sq2), 1e-12f);

    float prod = __fmul_rn(__fdiv_rn(sv, nr), __fdiv_rn(ev, nr2));
    float dot = 0.f;
#pragma unroll
    for (int d = 0; d < 32; d++) dot = __fadd_rn(dot, __shfl_sync(0xffffffffu, prod, d));

    if (lane == 0) {
        unsigned bits;
#if PARTITIONABLE
        unsigned o0, o1;
        tf2x32(0u, 7u, 0u, (unsigned)w, o0, o1);
        bits = o0 ^ o1;
#else
        unsigned o0, o1;
        if (w < HALF_N) { tf2x32(0u, 7u, (unsigned)w, (unsigned)(w + HALF_N), o0, o1); bits = o0; }
        else            { tf2x32(0u, 7u, (unsigned)(w - HALF_N), (unsigned)w, o0, o1); bits = o1; }
#endif
        float u = bits_to_uniform(bits);
        float lu = (float)log((double)u);
        float g  = -(float)log((double)(-lu));
        float score = __fadd_rn(dot, g);
        if (score_out) score_out[w] = score;
        unsigned ub = __float_as_uint(score);
        g_keys[w] = (ub & 0x80000000u) ? ~ub : (ub | 0x80000000u);
    }
}

// ---------------- top-k: radix select -> compact -> bitonic ----------------
__global__ void select_kernel() {
    __shared__ int hist[256];
    __shared__ unsigned s_prefix, s_mask;
    __shared__ int s_k;
    int tid = threadIdx.x;
    if (tid == 0) { s_prefix = 0u; s_mask = 0u; s_k = Kk; }
    __syncthreads();
    for (int shift = 24; shift >= 0; shift -= 8) {
        if (tid < 256) hist[tid] = 0;
        __syncthreads();
        unsigned mask = s_mask, pref = s_prefix;
        for (int i = tid; i < Nn; i += 1024) {
            unsigned key = g_keys[i];
            if ((key & mask) == pref) atomicAdd(&hist[(key >> shift) & 255u], 1);
        }
        __syncthreads();
        if (tid == 0) {
            int k = s_k;
            int v = 255;
            for (; v > 0; v--) { int c = hist[v]; if (k <= c) break; k -= c; }
            s_prefix = pref | ((unsigned)v << shift);
            s_mask = mask | (0xFFu << shift);
            s_k = k;
        }
        __syncthreads();
    }
    if (tid == 0) {
        g_kth = s_prefix;
        g_cntG = 0; g_cntE = 0;
    }
}

__global__ void compact_kernel() {
    int i = blockIdx.x * blockDim.x + threadIdx.x;
    if (i >= Nn) return;
    unsigned key = g_keys[i];
    unsigned T = g_kth;
    if (key > T) {
        int p = atomicAdd(&g_cntG, 1);
        if (p < 2048) g_candG[p] = (((unsigned long long)(~key)) << 32) | (unsigned)i;
    } else if (key == T) {
        int p = atomicAdd(&g_cntE, 1);
        if (p < 2048) g_candE[p] = i;
    }
}

__global__ void finalsort_kernel(float* cand_out) {
    __shared__ unsigned long long sg[1024];
    __shared__ int se[2048];
    int tid = threadIdx.x;
    int cntG = g_cntG; if (cntG > 1024) cntG = 1024;
    int cntE = g_cntE; if (cntE > 2048) cntE = 2048;
    sg[tid] = (tid < cntG) ? g_candG[tid] : 0xFFFFFFFFFFFFFFFFull;
    se[tid]        = (tid < cntE)        ? g_candE[tid]        : 0x7FFFFFFF;
    se[tid + 1024] = (tid + 1024 < cntE) ? g_candE[tid + 1024] : 0x7FFFFFFF;
    __syncthreads();
    for (int k = 2; k <= 1024; k <<= 1)
        for (int j = k >> 1; j > 0; j >>= 1) {
            int ixj = tid ^ j;
            if (ixj > tid) {
                bool up = ((tid & k) == 0);
                unsigned long long a = sg[tid], b = sg[ixj];
                if ((a > b) == up) { sg[tid] = b; sg[ixj] = a; }
            }
            __syncthreads();
        }
    for (int k = 2; k <= 2048; k <<= 1)
        for (int j = k >> 1; j > 0; j >>= 1) {
            for (int t = tid; t < 2048; t += 1024) {
                int ixj = t ^ j;
                if (ixj > t) {
                    bool up = ((t & k) == 0);
                    int a = se[t], b = se[ixj];
                    if ((a > b) == up) { se[t] = b; se[ixj] = a; }
                }
            }
            __syncthreads();
        }
    if (tid < Kk && cand_out) {
        int idx = (tid < cntG) ? (int)(sg[tid] & 0xFFFFFFFFull) : se[tid - cntG];
        cand_out[tid] = (float)idx;
    }
}

// ---------------- launch ----------------
extern "C" void kernel_launch(void* const* d_in, const int* in_sizes, int n_in,
                              void* d_out, int out_size) {
    const int*   edge_index = (const int*)d_in[0];   // [2, E]
    const float* adj_values = (const float*)d_in[1]; // [E]
    const float* embeds     = (const float*)d_in[2]; // [N, D]
    const int* rows = edge_index;
    const int* cols = edge_index + Ee;
    float* out = (float*)d_out;

    float* score_out = nullptr;
    float* cand_out  = nullptr;
    if (out_size >= Nn + Kk)      { score_out = out; cand_out = out + Nn; }
    else if (out_size == Nn)      { score_out = out; }
    else if (out_size == Kk)      { cand_out = out; }
    else                          { score_out = out; }

    unsigned fk[3][2];
    for (int i = 0; i < 3; i++) tf2x32(0u, 42u, 0u, (unsigned)i, fk[i][0], fk[i][1]);

    const int TB = 256;
    init_kernel<<<(Nn + TB - 1) / TB, TB>>>();
    count_kernel<<<(Ee + TB - 1) / TB, TB>>>(rows);
    scanA_kernel<<<NBLK, SCAN_B>>>();
    scanB_kernel<<<1, 128>>>();
    scanC_kernel<<<NBLK, SCAN_B>>>();
    scatter_kernel<<<(Ee + TB - 1) / TB, TB>>>(rows);
    sortfill_kernel<<<(Nn + TB - 1) / TB, TB>>>(cols, adj_values,
                                                fk[0][0], fk[0][1],
                                                fk[1][0], fk[1][1],
                                                fk[2][0], fk[2][1]);
    int warpBlocks = (Nn * 32 + TB - 1) / TB;
    emb0_kernel<<<warpBlocks, TB>>>(embeds);
    iter_kernel<0, 1><<<warpBlocks, TB>>>();
    iter_kernel<1, 2><<<warpBlocks, TB>>>();
    iter_kernel<0, 3><<<warpBlocks, TB>>>();
    score_kernel<<<warpBlocks, TB>>>(embeds, score_out);
    select_kernel<<<1, 1024>>>();
    compact_kernel<<<(Nn + TB - 1) / TB, TB>>>();
    finalsort_kernel<<<1, 1024>>>(cand_out);
}

// round 4
// speedup vs baseline: 1.2736x; 1.0434x over previous
#include <cuda_runtime.h>
#include <math.h>

#define Nn 100000
#define Ee 1600000
#define Dd 32
#define Kk 1024
#define HALF_E (Ee/2)
#define HALF_N (Nn/2)

#define PARTITIONABLE 1

#define SCAN_B 1024
#define NBLK ((Nn + SCAN_B - 1) / SCAN_B)   // 98

// ---------------- scratch ----------------
__device__ int      g_counts[Nn];
__device__ int      g_rowptr[Nn + 1];
__device__ int      g_cursor[Nn];
__device__ int      g_eid[Ee];
__device__ float2   g_cv0[Ee], g_cv1[Ee], g_cv2[Ee], g_cv3[Ee]; // (col, val) CSR order
__device__ float    g_order0[Nn], g_order1[Nn], g_order2[Nn];
__device__ float    g_embA[Nn * Dd], g_embB[Nn * Dd], g_embS[Nn * Dd];
__device__ float    g_numA[Nn], g_numB[Nn], g_numS[Nn];
__device__ unsigned g_keys[Nn];
__device__ unsigned g_kth;
__device__ int      g_cntG, g_cntE;
__device__ unsigned long long g_candG[2048];
__device__ int      g_candE[2048];
__device__ int      g_bsum[NBLK];
__device__ int      g_boff[NBLK + 1];

// ---------------- threefry-2x32 (JAX schedule) ----------------
__host__ __device__ __forceinline__ void tf2x32(unsigned k0, unsigned k1,
                                                unsigned x0, unsigned x1,
                                                unsigned& o0, unsigned& o1) {
    unsigned k2 = k0 ^ k1 ^ 0x1BD11BDAu;
    x0 += k0; x1 += k1;
#define TFR(r) { x0 += x1; x1 = (x1 << r) | (x1 >> (32 - r)); x1 ^= x0; }
    TFR(13) TFR(15) TFR(26) TFR(6)   x0 += k1; x1 += k2 + 1u;
    TFR(17) TFR(29) TFR(16) TFR(24)  x0 += k2; x1 += k0 + 2u;
    TFR(13) TFR(15) TFR(26) TFR(6)   x0 += k0; x1 += k1 + 3u;
    TFR(17) TFR(29) TFR(16) TFR(24)  x0 += k1; x1 += k2 + 4u;
    TFR(13) TFR(15) TFR(26) TFR(6)   x0 += k2; x1 += k0 + 5u;
#undef TFR
    o0 = x0; o1 = x1;
}

__device__ __forceinline__ float bits_to_uniform(unsigned bits) {
    return __fsub_rn(__uint_as_float((bits >> 9) | 0x3f800000u), 1.0f);
}

__device__ __forceinline__ unsigned edge_bits(unsigned k0, unsigned k1, int e) {
#if PARTITIONABLE
    unsigned o0, o1;
    tf2x32(k0, k1, 0u, (unsigned)e, o0, o1);
    return o0 ^ o1;
#else
    unsigned o0, o1;
    if (e < HALF_E) { tf2x32(k0, k1, (unsigned)e, (unsigned)(e + HALF_E), o0, o1); return o0; }
    else            { tf2x32(k0, k1, (unsigned)(e - HALF_E), (unsigned)e, o0, o1); return o1; }
#endif
}

__device__ __forceinline__ float2 packcv(int c, float v) {
    float2 r; r.x = __int_as_float(c); r.y = v; return r;
}

// ---------------- CSR build ----------------
__global__ void init_kernel() {
    int i = blockIdx.x * blockDim.x + threadIdx.x;
    if (i < Nn) g_counts[i] = 0;
}

__global__ void count_kernel(const int* __restrict__ rows) {
    int e = blockIdx.x * blockDim.x + threadIdx.x;
    if (e < Ee) atomicAdd(&g_counts[rows[e]], 1);
}

__global__ void scanA_kernel() {
    __shared__ int sh[SCAN_B];
    int tid = threadIdx.x;
    int idx = blockIdx.x * SCAN_B + tid;
    int v = (idx < Nn) ? g_counts[idx] : 0;
    sh[tid] = v;
    __syncthreads();
#pragma unroll
    for (int off = 1; off < SCAN_B; off <<= 1) {
        int t = (tid >= off) ? sh[tid - off] : 0;
        __syncthreads();
        sh[tid] += t;
        __syncthreads();
    }
    if (idx < Nn) g_rowptr[idx] = sh[tid] - v;
    if (tid == SCAN_B - 1) g_bsum[blockIdx.x] = sh[tid];
}

__global__ void scanB_kernel() {
    __shared__ int sh[NBLK];
    int tid = threadIdx.x;
    if (tid < NBLK) sh[tid] = g_bsum[tid];
    __syncthreads();
    if (tid == 0) {
        int acc = 0;
        for (int b = 0; b < NBLK; b++) { int t = sh[b]; g_boff[b] = acc; acc += t; }
        g_boff[NBLK] = acc;
        g_rowptr[Nn] = acc;
    }
}

__global__ void scanC_kernel() {
    int idx = blockIdx.x * SCAN_B + threadIdx.x;
    if (idx < Nn) {
        int v = g_rowptr[idx] + g_boff[blockIdx.x];
        g_rowptr[idx] = v;
        g_cursor[idx] = v;
    }
}

__global__ void scatter_kernel(const int* __restrict__ rows) {
    int e = blockIdx.x * blockDim.x + threadIdx.x;
    if (e >= Ee) return;
    int pos = atomicAdd(&g_cursor[rows[e]], 1);
    g_eid[pos] = e;
}

// ---------------- sortfill: WARP per row ----------------
// deg<=32: bitonic shfl sort of eids (no local mem), per-lane parallel threefry,
// strict lane-order shuffle-add for orders (bit-exact vs sequential edge-order sum;
// padding lanes contribute +0.0f to non-negative partials = bitwise no-op).
// deg>32 (rare, Poisson(16)): serial fallback on lane 0 (global insertion sort).
__global__ void sortfill_kernel(const int* __restrict__ cols,
                                const float* __restrict__ adj,
                                unsigned a0, unsigned a1, unsigned b0, unsigned b1,
                                unsigned c0, unsigned c1) {
    int w = (blockIdx.x * blockDim.x + threadIdx.x) >> 5;
    int lane = threadIdx.x & 31;
    if (w >= Nn) return;
    int s = g_rowptr[w], t = g_rowptr[w + 1];
    int deg = t - s;

    if (deg <= 32) {
        int eid = (lane < deg) ? g_eid[s + lane] : 0x7FFFFFFF;
        // bitonic ascending sort across the warp
#pragma unroll
        for (int k = 2; k <= 32; k <<= 1) {
#pragma unroll
            for (int j = k >> 1; j > 0; j >>= 1) {
                int other = __shfl_xor_sync(0xffffffffu, eid, j);
                bool up = ((lane & k) == 0);
                bool lower = ((lane & j) == 0);
                int mn = min(eid, other), mx = max(eid, other);
                eid = ((lower == up)) ? mn : mx;
            }
        }
        int   c  = 0;
        float v0 = 0.f, v1 = 0.f, v2 = 0.f, v3 = 0.f;
        if (lane < deg) {
            c  = cols[eid];
            v0 = adj[eid];
            float k0f = floorf(__fadd_rn(bits_to_uniform(edge_bits(a0, a1, eid)), 0.5f));
            v1 = __fmul_rn(v0, k0f);
            float k1f = floorf(__fadd_rn(bits_to_uniform(edge_bits(b0, b1, eid)), 0.25f));
            v2 = __fmul_rn(v1, k1f);
            float k2f = floorf(__fadd_rn(bits_to_uniform(edge_bits(c0, c1, eid)), 0.125f));
            v3 = __fmul_rn(v2, k2f);
            g_cv0[s + lane] = packcv(c, v0);
            g_cv1[s + lane] = packcv(c, v1);
            g_cv2[s + lane] = packcv(c, v2);
            g_cv3[s + lane] = packcv(c, v3);
        }
        // strict lane-order sums
        float o0a = 0.f, o1a = 0.f, o2a = 0.f;
#pragma unroll
        for (int d = 0; d < 32; d++) {
            o0a = __fadd_rn(o0a, __shfl_sync(0xffffffffu, v0, d));
            o1a = __fadd_rn(o1a, __shfl_sync(0xffffffffu, v1, d));
            o2a = __fadd_rn(o2a, __shfl_sync(0xffffffffu, v2, d));
        }
        if (lane == 0) { g_order0[w] = o0a; g_order1[w] = o1a; g_order2[w] = o2a; }
    } else if (lane == 0) {
        // serial fallback: global in-place insertion sort + sequential chain
        for (int a = s + 1; a < t; a++) {
            int x = g_eid[a]; int b = a - 1;
            while (b >= s && g_eid[b] > x) { g_eid[b + 1] = g_eid[b]; b--; }
            g_eid[b + 1] = x;
        }
        float o0a = 0.f, o1a = 0.f, o2a = 0.f;
        for (int q = s; q < t; q++) {
            int eid = g_eid[q];
            int c = cols[eid];
            float v0 = adj[eid];
            float k0f = floorf(__fadd_rn(bits_to_uniform(edge_bits(a0, a1, eid)), 0.5f));
            float v1 = __fmul_rn(v0, k0f);
            float k1f = floorf(__fadd_rn(bits_to_uniform(edge_bits(b0, b1, eid)), 0.25f));
            float v2 = __fmul_rn(v1, k1f);
            float k2f = floorf(__fadd_rn(bits_to_uniform(edge_bits(c0, c1, eid)), 0.125f));
            float v3 = __fmul_rn(v2, k2f);
            g_cv0[q] = packcv(c, v0);
            g_cv1[q] = packcv(c, v1);
            g_cv2[q] = packcv(c, v2);
            g_cv3[q] = packcv(c, v3);
            o0a = __fadd_rn(o0a, v0);
            o1a = __fadd_rn(o1a, v1);
            o2a = __fadd_rn(o2a, v2);
        }
        g_order0[w] = o0a; g_order1[w] = o1a; g_order2[w] = o2a;
    }
}

// ---------------- propagation ----------------
// Unroll-8: batched loads for MLP; add order strictly sequential in p.
__global__ void emb0_kernel(const float* __restrict__ X) {
    int w = (blockIdx.x * blockDim.x + threadIdx.x) >> 5;
    int lane = threadIdx.x & 31;
    if (w >= Nn) return;
    int s = g_rowptr[w], t = g_rowptr[w + 1];
    float acc = 0.f;
    int p = s;
    for (; p + 8 <= t; p += 8) {
        float2 a[8];
        float  x[8];
#pragma unroll
        for (int i = 0; i < 8; i++) a[i] = g_cv0[p + i];
#pragma unroll
        for (int i = 0; i < 8; i++) x[i] = X[__float_as_int(a[i].x) * Dd + lane];
#pragma unroll
        for (int i = 0; i < 8; i++) acc = __fadd_rn(acc, __fmul_rn(a[i].y, x[i]));
    }
    for (; p + 4 <= t; p += 4) {
        float2 a[4];
        float  x[4];
#pragma unroll
        for (int i = 0; i < 4; i++) a[i] = g_cv0[p + i];
#pragma unroll
        for (int i = 0; i < 4; i++) x[i] = X[__float_as_int(a[i].x) * Dd + lane];
#pragma unroll
        for (int i = 0; i < 4; i++) acc = __fadd_rn(acc, __fmul_rn(a[i].y, x[i]));
    }
    for (; p < t; p++) {
        float2 a = g_cv0[p];
        acc = __fadd_rn(acc, __fmul_rn(a.y, X[__float_as_int(a.x) * Dd + lane]));
    }
    float e0 = __fsub_rn(acc, X[w * Dd + lane]);
    g_embA[w * Dd + lane] = e0;
    g_embS[w * Dd + lane] = e0;
    if (lane == 0) {
        float o = g_order0[w];
        g_numA[w] = o;
        g_numS[w] = o;
    }
}

template <int SEL, int COMP>
__global__ void iter_kernel() {
    const float2* __restrict__ cv = (COMP == 1) ? g_cv1 : ((COMP == 2) ? g_cv2 : g_cv3);
    const float* __restrict__ ord = (COMP == 1) ? g_order0 : ((COMP == 2) ? g_order1 : g_order2);
    const float* __restrict__ cur  = SEL ? g_embB : g_embA;
    float*       __restrict__ nxt  = SEL ? g_embA : g_embB;
    const float* __restrict__ curn = SEL ? g_numB : g_numA;
    float*       __restrict__ nxtn = SEL ? g_numA : g_numB;
    int w = (blockIdx.x * blockDim.x + threadIdx.x) >> 5;
    int lane = threadIdx.x & 31;
    if (w >= Nn) return;
    int s = g_rowptr[w], t = g_rowptr[w + 1];
    float accE = 0.f, accN = 0.f;
    int p = s;
    for (; p + 8 <= t; p += 8) {
        float2 a[8];
        float  x[8], n[8];
#pragma unroll
        for (int i = 0; i < 8; i++) a[i] = cv[p + i];
#pragma unroll
        for (int i = 0; i < 8; i++) {
            int c = __float_as_int(a[i].x);
            x[i] = cur[c * Dd + lane];
            n[i] = curn[c];
        }
#pragma unroll
        for (int i = 0; i < 8; i++) {
            accE = __fadd_rn(accE, __fmul_rn(a[i].y, x[i]));
            accN = __fadd_rn(accN, __fmul_rn(a[i].y, n[i]));
        }
    }
    for (; p + 4 <= t; p += 4) {
        float2 a[4];
        float  x[4], n[4];
#pragma unroll
        for (int i = 0; i < 4; i++) a[i] = cv[p + i];
#pragma unroll
        for (int i = 0; i < 4; i++) {
            int c = __float_as_int(a[i].x);
            x[i] = cur[c * Dd + lane];
            n[i] = curn[c];
        }
#pragma unroll
        for (int i = 0; i < 4; i++) {
            accE = __fadd_rn(accE, __fmul_rn(a[i].y, x[i]));
            accN = __fadd_rn(accN, __fmul_rn(a[i].y, n[i]));
        }
    }
    for (; p < t; p++) {
        float2 a = cv[p];
        int c = __float_as_int(a.x);
        accE = __fadd_rn(accE, __fmul_rn(a.y, cur[c * Dd + lane]));
        accN = __fadd_rn(accN, __fmul_rn(a.y, curn[c]));
    }
    float o = ord[w];
    float ce = cur[w * Dd + lane];
    float outE = __fsub_rn(__fsub_rn(accE, ce), __fmul_rn(o, ce));
    nxt[w * Dd + lane] = outE;
    g_embS[w * Dd + lane] = __fadd_rn(g_embS[w * Dd + lane], outE);
    if (lane == 0) {
        float cn = curn[w];
        float outN = __fsub_rn(__fsub_rn(accN, cn), o);
        nxtn[w] = outN;
        g_numS[w] = __fadd_rn(g_numS[w], outN);
    }
}

// ---------------- scores ----------------
__global__ void score_kernel(const float* __restrict__ X, float* score_out) {
    int w = (blockIdx.x * blockDim.x + threadIdx.x) >> 5;
    int lane = threadIdx.x & 31;
    if (w >= Nn) return;
    float den = __fadd_rn(g_numS[w], 1e-8f);
    float sv = __fdiv_rn(g_embS[w * Dd + lane], den);
    float ev = X[w * Dd + lane];

    float p1 = __fmul_rn(sv, sv);
    float sq = 0.f;
#pragma unroll
    for (int d = 0; d < 32; d++) sq = __fadd_rn(sq, __shfl_sync(0xffffffffu, p1, d));
    float nr = fmaxf(__fsqrt_rn(sq), 1e-12f);

    float p2 = __fmul_rn(ev, ev);
    float sq2 = 0.f;
#pragma unroll
    for (int d = 0; d < 32; d++) sq2 = __fadd_rn(sq2, __shfl_sync(0xffffffffu, p2, d));
    float nr2 = fmaxf(__fsqrt_rn(sq2), 1e-12f);

    float prod = __fmul_rn(__fdiv_rn(sv, nr), __fdiv_rn(ev, nr2));
    float dot = 0.f;
#pragma unroll
    for (int d = 0; d < 32; d++) dot = __fadd_rn(dot, __shfl_sync(0xffffffffu, prod, d));

    if (lane == 0) {
        unsigned bits;
#if PARTITIONABLE
        unsigned o0, o1;
        tf2x32(0u, 7u, 0u, (unsigned)w, o0, o1);
        bits = o0 ^ o1;
#else
        unsigned o0, o1;
        if (w < HALF_N) { tf2x32(0u, 7u, (unsigned)w, (unsigned)(w + HALF_N), o0, o1); bits = o0; }
        else            { tf2x32(0u, 7u, (unsigned)(w - HALF_N), (unsigned)w, o0, o1); bits = o1; }
#endif
        float u = bits_to_uniform(bits);
        float lu = (float)log((double)u);
        float g  = -(float)log((double)(-lu));
        float score = __fadd_rn(dot, g);
        if (score_out) score_out[w] = score;
        unsigned ub = __float_as_uint(score);
        g_keys[w] = (ub & 0x80000000u) ? ~ub : (ub | 0x80000000u);
    }
}

// ---------------- top-k ----------------
__global__ void select_kernel() {
    __shared__ int hist[256];
    __shared__ unsigned s_prefix, s_mask;
    __shared__ int s_k;
    int tid = threadIdx.x;
    if (tid == 0) { s_prefix = 0u; s_mask = 0u; s_k = Kk; }
    __syncthreads();
    for (int shift = 24; shift >= 0; shift -= 8) {
        if (tid < 256) hist[tid] = 0;
        __syncthreads();
        unsigned mask = s_mask, pref = s_prefix;
        for (int i = tid; i < Nn; i += 1024) {
            unsigned key = g_keys[i];
            if ((key & mask) == pref) atomicAdd(&hist[(key >> shift) & 255u], 1);
        }
        __syncthreads();
        if (tid == 0) {
            int k = s_k;
            int v = 255;
            for (; v > 0; v--) { int c = hist[v]; if (k <= c) break; k -= c; }
            s_prefix = pref | ((unsigned)v << shift);
            s_mask = mask | (0xFFu << shift);
            s_k = k;
        }
        __syncthreads();
    }
    if (tid == 0) {
        g_kth = s_prefix;
        g_cntG = 0; g_cntE = 0;
    }
}

__global__ void compact_kernel() {
    int i = blockIdx.x * blockDim.x + threadIdx.x;
    if (i >= Nn) return;
    unsigned key = g_keys[i];
    unsigned T = g_kth;
    if (key > T) {
        int p = atomicAdd(&g_cntG, 1);
        if (p < 2048) g_candG[p] = (((unsigned long long)(~key)) << 32) | (unsigned)i;
    } else if (key == T) {
        int p = atomicAdd(&g_cntE, 1);
        if (p < 2048) g_candE[p] = i;
    }
}

__global__ void finalsort_kernel(float* cand_out) {
    __shared__ unsigned long long sg[1024];
    __shared__ int se[2048];
    int tid = threadIdx.x;
    int cntG = g_cntG; if (cntG > 1024) cntG = 1024;
    int cntE = g_cntE; if (cntE > 2048) cntE = 2048;
    sg[tid] = (tid < cntG) ? g_candG[tid] : 0xFFFFFFFFFFFFFFFFull;
    se[tid]        = (tid < cntE)        ? g_candE[tid]        : 0x7FFFFFFF;
    se[tid + 1024] = (tid + 1024 < cntE) ? g_candE[tid + 1024] : 0x7FFFFFFF;
    __syncthreads();
    for (int k = 2; k <= 1024; k <<= 1)
        for (int j = k >> 1; j > 0; j >>= 1) {
            int ixj = tid ^ j;
            if (ixj > tid) {
                bool up = ((tid & k) == 0);
                unsigned long long a = sg[tid], b = sg[ixj];
                if ((a > b) == up) { sg[tid] = b; sg[ixj] = a; }
            }
            __syncthreads();
        }
    for (int k = 2; k <= 2048; k <<= 1)
        for (int j = k >> 1; j > 0; j >>= 1) {
            for (int t = tid; t < 2048; t += 1024) {
                int ixj = t ^ j;
                if (ixj > t) {
                    bool up = ((t & k) == 0);
                    int a = se[t], b = se[ixj];
                    if ((a > b) == up) { se[t] = b; se[ixj] = a; }
                }
            }
            __syncthreads();
        }
    if (tid < Kk && cand_out) {
        int idx = (tid < cntG) ? (int)(sg[tid] & 0xFFFFFFFFull) : se[tid - cntG];
        cand_out[tid] = (float)idx;
    }
}

// ---------------- launch ----------------
extern "C" void kernel_launch(void* const* d_in, const int* in_sizes, int n_in,
                              void* d_out, int out_size) {
    const int*   edge_index = (const int*)d_in[0];
    const float* adj_values = (const float*)d_in[1];
    const float* embeds     = (const float*)d_in[2];
    const int* rows = edge_index;
    const int* cols = edge_index + Ee;
    float* out = (float*)d_out;

    float* score_out = nullptr;
    float* cand_out  = nullptr;
    if (out_size >= Nn + Kk)      { score_out = out; cand_out = out + Nn; }
    else if (out_size == Nn)      { score_out = out; }
    else if (out_size == Kk)      { cand_out = out; }
    else                          { score_out = out; }

    unsigned fk[3][2];
    for (int i = 0; i < 3; i++) tf2x32(0u, 42u, 0u, (unsigned)i, fk[i][0], fk[i][1]);

    const int TB = 256;
    int warpBlocks = (Nn * 32 + TB - 1) / TB;
    init_kernel<<<(Nn + TB - 1) / TB, TB>>>();
    count_kernel<<<(Ee + TB - 1) / TB, TB>>>(rows);
    scanA_kernel<<<NBLK, SCAN_B>>>();
    scanB_kernel<<<1, 128>>>();
    scanC_kernel<<<NBLK, SCAN_B>>>();
    scatter_kernel<<<(Ee + TB - 1) / TB, TB>>>(rows);
    sortfill_kernel<<<warpBlocks, TB>>>(cols, adj_values,
                                        fk[0][0], fk[0][1],
                                        fk[1][0], fk[1][1],
                                        fk[2][0], fk[2][1]);
    emb0_kernel<<<warpBlocks, TB>>>(embeds);
    iter_kernel<0, 1><<<warpBlocks, TB>>>();
    iter_kernel<1, 2><<<warpBlocks, TB>>>();
    iter_kernel<0, 3><<<warpBlocks, TB>>>();
    score_kernel<<<warpBlocks, TB>>>(embeds, score_out);
    select_kernel<<<1, 1024>>>();
    compact_kernel<<<(Nn + TB - 1) / TB, TB>>>();
    finalsort_kernel<<<1, 1024>>>(cand_out);
}